// round 1
// baseline (speedup 1.0000x reference)
#include <cuda_runtime.h>

// Problem: N=65536 rows. Per row n:
//   m = max_k |dot(x[n,k,:], y[n,0,:])|   (K=1024, D=4)
//   if m > 0.9999999 -> m = 1.0
//   d[n] = 2*acos(m)          (min over k of 2*acos(cost) == 2*acos(max cost))
// out = sum(d) / N
//
// Inputs (metadata order): d_in[0]=y (N,1,4) f32, d_in[1]=w_y (N,K) f32 (UNUSED),
//                          d_in[2]=x (N,K,4) f32. Output: 1 f32 scalar.

#define N_ROWS   65536
#define K_DIM    1024
#define WARPS_PER_BLOCK 8
#define THREADS  (WARPS_PER_BLOCK * 32)
#define NBLOCKS  (N_ROWS / WARPS_PER_BLOCK)   // 8192

__device__ float g_partials[NBLOCKS];

__global__ __launch_bounds__(THREADS)
void rowmax_kernel(const float* __restrict__ y,
                   const float* __restrict__ x)
{
    const int warp_in_blk = threadIdx.x >> 5;
    const int lane        = threadIdx.x & 31;
    const int n           = blockIdx.x * WARPS_PER_BLOCK + warp_in_blk;

    // y0 for this row: all lanes read the same float4 (L1 broadcast)
    const float4 y0 = reinterpret_cast<const float4*>(y)[n];

    const float4* xp = reinterpret_cast<const float4*>(x) + (size_t)n * K_DIM;

    float m = 0.0f;
    #pragma unroll 8
    for (int i = 0; i < K_DIM / 32; ++i) {
        float4 v = __ldg(&xp[lane + 32 * i]);
        float dot = fabsf(v.x * y0.x + v.y * y0.y + v.z * y0.z + v.w * y0.w);
        m = fmaxf(m, dot);
    }

    // warp max-reduce
    #pragma unroll
    for (int off = 16; off > 0; off >>= 1)
        m = fmaxf(m, __shfl_xor_sync(0xFFFFFFFFu, m, off));

    __shared__ float s_d[WARPS_PER_BLOCK];
    if (lane == 0) {
        if (m > 0.9999999f) m = 1.0f;
        s_d[warp_in_blk] = 2.0f * acosf(m);
    }
    __syncthreads();

    if (threadIdx.x == 0) {
        float t = 0.0f;
        #pragma unroll
        for (int i = 0; i < WARPS_PER_BLOCK; ++i) t += s_d[i];
        g_partials[blockIdx.x] = t;
    }
}

__global__ __launch_bounds__(1024)
void reduce_kernel(float* __restrict__ out)
{
    const int tid = threadIdx.x;
    float t = 0.0f;
    #pragma unroll
    for (int i = tid; i < NBLOCKS; i += 1024)
        t += g_partials[i];

    // block reduce (1024 threads)
    #pragma unroll
    for (int off = 16; off > 0; off >>= 1)
        t += __shfl_xor_sync(0xFFFFFFFFu, t, off);

    __shared__ float s[32];
    if ((tid & 31) == 0) s[tid >> 5] = t;
    __syncthreads();
    if (tid < 32) {
        float v = s[tid];
        #pragma unroll
        for (int off = 16; off > 0; off >>= 1)
            v += __shfl_xor_sync(0xFFFFFFFFu, v, off);
        if (tid == 0) out[0] = v / (float)N_ROWS;
    }
}

extern "C" void kernel_launch(void* const* d_in, const int* in_sizes, int n_in,
                              void* d_out, int out_size)
{
    const float* y = (const float*)d_in[0];
    // d_in[1] = w_y : unused by the reference reduction
    const float* x = (const float*)d_in[2];
    float* out = (float*)d_out;

    rowmax_kernel<<<NBLOCKS, THREADS>>>(y, x);
    reduce_kernel<<<1, 1024>>>(out);
}

// round 2
// speedup vs baseline: 1.0257x; 1.0257x over previous
#include <cuda_runtime.h>

// Problem: N=65536 rows. Per row n:
//   m = max_k |dot(x[n,k,:], y[n,0,:])|   (K=1024, D=4)
//   if m > 0.9999999 -> m = 1.0   (cost >= 0, so LOWER clamp is dead)
//   d[n] = 2*acos(m)              (acos monotone decreasing => min over k of
//                                  2*acos(cost) == 2*acos(max_k cost))
// out = sum(d) / N
//
// Inputs (metadata order): d_in[0]=y (N,1,4) f32, d_in[1]=w_y (N,K) f32 (UNUSED),
//                          d_in[2]=x (N,K,4) f32. Output: 1 f32 scalar.
//
// Single fused kernel: streaming rowmax + per-block partial, last arriving
// block (ticket counter) reduces all partials in fixed index order ->
// deterministic, graph-capturable, allocation-free.

#define N_ROWS   65536
#define K_DIM    1024
#define WARPS_PER_BLOCK 8
#define THREADS  (WARPS_PER_BLOCK * 32)
#define NBLOCKS  (N_ROWS / WARPS_PER_BLOCK)   // 8192

__device__ float        g_partials[NBLOCKS];
__device__ unsigned int g_ticket = 0;          // self-resetting each launch

__global__ __launch_bounds__(THREADS)
void fused_kernel(const float* __restrict__ y,
                  const float* __restrict__ x,
                  float* __restrict__ out)
{
    const int warp_in_blk = threadIdx.x >> 5;
    const int lane        = threadIdx.x & 31;
    const int n           = blockIdx.x * WARPS_PER_BLOCK + warp_in_blk;

    // y0 for this row: all lanes of the warp read the same float4 (broadcast)
    const float4 y0 = reinterpret_cast<const float4*>(y)[n];

    const float4* xp = reinterpret_cast<const float4*>(x) + (size_t)n * K_DIM;

    float m = 0.0f;
    #pragma unroll 8
    for (int i = 0; i < K_DIM / 32; ++i) {
        float4 v = __ldcs(&xp[lane + 32 * i]);   // streamed once: evict-first
        float dot = fabsf(v.x * y0.x + v.y * y0.y + v.z * y0.z + v.w * y0.w);
        m = fmaxf(m, dot);
    }

    // warp max-reduce
    #pragma unroll
    for (int off = 16; off > 0; off >>= 1)
        m = fmaxf(m, __shfl_xor_sync(0xFFFFFFFFu, m, off));

    __shared__ float s_d[WARPS_PER_BLOCK];
    if (lane == 0) {
        if (m > 0.9999999f) m = 1.0f;
        s_d[warp_in_blk] = 2.0f * acosf(m);
    }
    __syncthreads();

    __shared__ bool s_last;
    if (threadIdx.x == 0) {
        float t = 0.0f;
        #pragma unroll
        for (int i = 0; i < WARPS_PER_BLOCK; ++i) t += s_d[i];
        g_partials[blockIdx.x] = t;
        __threadfence();                               // publish partial
        unsigned int tk = atomicAdd(&g_ticket, 1u);
        s_last = (tk == NBLOCKS - 1);
    }
    __syncthreads();

    if (!s_last) return;

    // ---- last block: deterministic final reduction over g_partials ----
    const int tid = threadIdx.x;
    float t = 0.0f;
    #pragma unroll
    for (int i = tid; i < NBLOCKS; i += THREADS)
        t += __ldcg(&g_partials[i]);                   // L2-coherent read

    #pragma unroll
    for (int off = 16; off > 0; off >>= 1)
        t += __shfl_xor_sync(0xFFFFFFFFu, t, off);

    __shared__ float s_w[WARPS_PER_BLOCK];
    if (lane == 0) s_w[warp_in_blk] = t;
    __syncthreads();

    if (tid == 0) {
        float v = 0.0f;
        #pragma unroll
        for (int i = 0; i < WARPS_PER_BLOCK; ++i) v += s_w[i];
        out[0] = v / (float)N_ROWS;
        g_ticket = 0;                                  // reset for next replay
    }
}

extern "C" void kernel_launch(void* const* d_in, const int* in_sizes, int n_in,
                              void* d_out, int out_size)
{
    const float* y = (const float*)d_in[0];
    // d_in[1] = w_y : unused by the reference reduction
    const float* x = (const float*)d_in[2];
    float* out = (float*)d_out;

    fused_kernel<<<NBLOCKS, THREADS>>>(y, x, out);
}